// round 14
// baseline (speedup 1.0000x reference)
#include <cuda_runtime.h>
#include <cuda_fp16.h>
#include <cstdint>

#define H        4096
#define T_TRAIN  2048
#define GRID     148
#define BLOCK    1024         // 28 dot warps + 4 stager/helper warps
#define DOTW     28
#define HMAX     64
#define NCACHE   27           // U-matrix rows cached in SMEM per CTA (big path)
#define ROW_U4   512          // uint4 per weight row (4096 halves = 8 KB)
#define H2_U4    512          // uint4 of packed fp16 h (4096 halves = 8 KB)

// ---------------- persistent device state ----------------------------------
__device__ __half   g_wu[(size_t)H * H];   // fp16 weights, PERMUTED layout:
__device__ __half   g_wr[(size_t)H * H];   // chunk j = cols {4j..4j+3, 2048+4j..2048+4j+3}
__device__ __half   g_wc[(size_t)H * H];
__device__ float    g_h[2][H];             // fp32 hidden-state chain (accuracy-critical)
__device__ float    g_vhp[HMAX + 1][GRID];
__device__ unsigned g_count;               // centralized barrier (R8-proven)
__device__ unsigned g_phase;

// ---------------- fp32 -> fp16 conversion with column permutation -----------
__global__ void convert_w(const float* __restrict__ u,
                          const float* __restrict__ r,
                          const float* __restrict__ c)
{
    const int total = H * ROW_U4;
    int idx = blockIdx.x * blockDim.x + threadIdx.x;
    if (idx >= total) return;
    const int row = idx >> 9;
    const int j   = idx & 511;
    const int i0  = row * (H / 4) + j;        // float4 index of cols 4j..4j+3
    const int i1  = i0 + 512;                 // float4 index of cols 2048+4j..+3

    #define CVT_ONE(SRC, DST)                                           \
    {                                                                   \
        float4 a = ((const float4*)SRC)[i0];                            \
        float4 b = ((const float4*)SRC)[i1];                            \
        uint4 o;                                                        \
        __half2 t;                                                      \
        t = __floats2half2_rn(a.x, a.y); o.x = *(unsigned*)&t;          \
        t = __floats2half2_rn(a.z, a.w); o.y = *(unsigned*)&t;          \
        t = __floats2half2_rn(b.x, b.y); o.z = *(unsigned*)&t;          \
        t = __floats2half2_rn(b.z, b.w); o.w = *(unsigned*)&t;          \
        ((uint4*)DST)[idx] = o;                                         \
    }
    CVT_ONE(u, g_wu)
    CVT_ONE(r, g_wr)
    CVT_ONE(c, g_wc)
    #undef CVT_ONE
}

// ---------------- grid-wide barrier (R8-proven centralized version) ----------
__device__ __forceinline__ void grid_barrier(unsigned &local_phase, int G) {
    __threadfence();
    __syncthreads();
    if (threadIdx.x == 0) {
        unsigned target = local_phase + 1;
        unsigned arrived = atomicAdd(&g_count, 1u) + 1;
        if (arrived == (unsigned)G) {
            atomicExch(&g_count, 0u);
            __threadfence();
            atomicAdd(&g_phase, 1u);
        } else {
            volatile unsigned* ph = &g_phase;
            while (*ph < target) { }
        }
    }
    local_phase++;
    __syncthreads();
    __threadfence();
}

__device__ __forceinline__ float sigmoidf_fast(float z) {
    return 1.0f / (1.0f + __expf(-z));
}

// packed f32x2 add: acc(lo,hi) += (x0,x1); acc carried as u64
__device__ __forceinline__ void fadd2(unsigned long long& acc, float x0, float x1)
{
    unsigned long long a;
    asm("mov.b64 %0, {%1, %2};" : "=l"(a) : "f"(x0), "f"(x1));
    asm("add.rn.f32x2 %0, %1, %2;" : "=l"(acc) : "l"(acc), "l"(a));
}

__device__ __forceinline__ float hsum2(unsigned long long acc) {
    float lo, hi;
    asm("mov.b64 {%0, %1}, %2;" : "=f"(lo), "=f"(hi) : "l"(acc));
    return lo + hi;
}

__device__ __forceinline__ __half2 u2h2(unsigned v) { return *(__half2*)&v; }

// 8-element packed-half partial dot: (w uint4) . (h uint4) -> float2
__device__ __forceinline__ float2 dot8h(uint4 w, uint4 h)
{
    __half2 p = __hmul2(u2h2(w.x), u2h2(h.x));
    p = __hfma2(u2h2(w.y), u2h2(h.y), p);
    p = __hfma2(u2h2(w.z), u2h2(h.z), p);
    p = __hfma2(u2h2(w.w), u2h2(h.w), p);
    return __half22float2(p);
}

// spin on 4 per-stager-warp step flags (values are monotone step numbers)
__device__ __forceinline__ void wait_flags(volatile int* f, int t) {
    while (f[0] < t || f[1] < t || f[2] < t || f[3] < t) { }
}

// ---------------- persistent GRU kernel -------------------------------------
__global__ void __launch_bounds__(BLOCK, 1)
gru_persistent(const float* __restrict__ x_seq,
               const float* __restrict__ uwx, const float* __restrict__ ub,
               const float* __restrict__ rwx, const float* __restrict__ rb,
               const float* __restrict__ wx,  const float* __restrict__ bb,
               const float* __restrict__ v,   const float* __restrict__ cc,
               float* __restrict__ out, int horizon, int ncache)
{
    extern __shared__ char smem[];
    uint4* h2s = (uint4*)smem;                          // 8 KB packed fp16 h
    uint4* ws  = (uint4*)(smem + H2_U4 * sizeof(uint4)); // ncache rows of U

    __shared__ float red_s[32];
    __shared__ float gc_s[7][DOTW];      // gate constants per owned row
    __shared__ float prc_s[2][DOTW];     // stager partials: [0]=R, [1]=C (batches 14-15)
    __shared__ float x_s;
    __shared__ int   flA[4], flB[4];     // h-chunk flags
    __shared__ int   flP[4];             // stager-partial flags
    __shared__ int   flX;                // x-ready flag

    const int tid  = threadIdx.x;
    const int b    = blockIdx.x;
    const int G    = gridDim.x;
    const int warp = tid >> 5;
    const int lane = tid & 31;

    const int r0 = (int)(((long long)b       * H) / G);
    const int r1 = (int)(((long long)(b + 1) * H) / G);
    const int nrows = r1 - r0;   // 27 or 28 (<= DOTW)

    if (tid < 4) { flA[tid] = -1; flB[tid] = -1; flP[tid] = -1; }
    if (tid == 4) flX = -1;
    if (tid < 32) red_s[tid] = 0.f;
    // stage gate constants into SMEM (row r0+i -> column i)
    if (tid < nrows) {
        const int row = r0 + tid;
        gc_s[0][tid] = uwx[row]; gc_s[1][tid] = ub[row];
        gc_s[2][tid] = rwx[row]; gc_s[3][tid] = rb[row];
        gc_s[4][tid] = wx[row];  gc_s[5][tid] = bb[row];
        gc_s[6][tid] = v[row];
    }

    // prologue: pin first `ncache` U-rows of this CTA into SMEM
    {
        const uint4* src = ((const uint4*)g_wu) + (size_t)r0 * ROW_U4;
        const int n = ncache * ROW_U4;
        for (int i = tid; i < n; i += BLOCK) ws[i] = src[i];
    }

    // matvec row pointers (warp w owns row r0+w for all three matrices)
    const bool mv_active = (warp < nrows);
    const int  myrow = r0 + warp;
    const uint4* pu = nullptr; const uint4* pr = nullptr; const uint4* pc = nullptr;
    if (mv_active) {
        const size_t off = (size_t)myrow * ROW_U4;
        pu = (warp < ncache) ? (ws + (size_t)warp * ROW_U4)
                             : (((const uint4*)g_wu) + off);
        pr = ((const uint4*)g_wr) + off;
        pc = ((const uint4*)g_wc) + off;
    }

    const float c0 = cc[0];
    unsigned phase = 0;
    const int total_steps = T_TRAIN + horizon;
    __syncthreads();   // flags/constants/ws visible to all warps

    for (int t = 0; t < total_steps; ++t) {
        const int par = t & 1;
        const float* hin  = g_h[par];
        float*       hout = g_h[par ^ 1];
        const bool need_y = (t >= T_TRAIN - 1);

        if (warp >= DOTW) {
            // ---- stager warps: stage h, then compute R/C batch-14..15 partials ----
            const int sw  = warp - DOTW;        // 0..3
            const int sid = tid - DOTW * 32;    // 0..127

            // warp 31: publish x FIRST so dot warps never wait at the tail
            if (warp == 31) {
                if (t < T_TRAIN) {
                    if (lane == 0) {
                        x_s = x_seq[t];
                        __threadfence_block();
                        flX = t;
                    }
                } else {
                    const float* p = g_vhp[t - T_TRAIN];
                    float s = 0.f;
                    for (int i = lane; i < G; i += 32) s += p[i];
                    #pragma unroll
                    for (int o = 16; o; o >>= 1)
                        s += __shfl_down_sync(0xffffffffu, s, o);
                    if (lane == 0) {
                        x_s = s + c0;
                        __threadfence_block();
                        flX = t;
                    }
                }
            }

            const float4* src = (const float4*)hin;
            // chunk A: j in [0,256)  (dot batches k<8)
            #pragma unroll
            for (int i = sid; i < 256; i += 128) {
                float4 a = src[i];
                float4 bq = src[512 + i];
                uint4 o; __half2 tt;
                tt = __floats2half2_rn(a.x,  a.y);  o.x = *(unsigned*)&tt;
                tt = __floats2half2_rn(a.z,  a.w);  o.y = *(unsigned*)&tt;
                tt = __floats2half2_rn(bq.x, bq.y); o.z = *(unsigned*)&tt;
                tt = __floats2half2_rn(bq.z, bq.w); o.w = *(unsigned*)&tt;
                h2s[i] = o;
            }
            __syncwarp();
            __threadfence_block();
            if (lane == 0) flA[sw] = t;
            // chunk B: j in [256,512)  (dot batches k>=8)
            #pragma unroll
            for (int i = sid + 256; i < 512; i += 128) {
                float4 a = src[i];
                float4 bq = src[512 + i];
                uint4 o; __half2 tt;
                tt = __floats2half2_rn(a.x,  a.y);  o.x = *(unsigned*)&tt;
                tt = __floats2half2_rn(a.z,  a.w);  o.y = *(unsigned*)&tt;
                tt = __floats2half2_rn(bq.x, bq.y); o.z = *(unsigned*)&tt;
                tt = __floats2half2_rn(bq.z, bq.w); o.w = *(unsigned*)&tt;
                h2s[i] = o;
            }
            __syncwarp();
            __threadfence_block();
            if (lane == 0) flB[sw] = t;

            // ---- offloaded partial dots: R and C, batches 14-15, 7 rows ----
            wait_flags(flB, t);                 // all of chunk B staged
            const uint4 hh14 = h2s[lane + 448]; // batch 14
            const uint4 hh15 = h2s[lane + 480]; // batch 15
            #pragma unroll
            for (int rr = 0; rr < 7; ++rr) {
                const int lr = 7 * sw + rr;
                if (lr < nrows) {
                    const size_t off = (size_t)(r0 + lr) * ROW_U4;
                    const uint4* prw = ((const uint4*)g_wr) + off;
                    const uint4* pcw = ((const uint4*)g_wc) + off;
                    unsigned long long aR = 0ull, aC = 0ull;
                    float2 f;
                    f = dot8h(prw[lane + 448], hh14); fadd2(aR, f.x, f.y);
                    f = dot8h(prw[lane + 480], hh15); fadd2(aR, f.x, f.y);
                    f = dot8h(pcw[lane + 448], hh14); fadd2(aC, f.x, f.y);
                    f = dot8h(pcw[lane + 480], hh15); fadd2(aC, f.x, f.y);
                    float sR = hsum2(aR), sC = hsum2(aC);
                    #pragma unroll
                    for (int o = 16; o; o >>= 1) {
                        sR += __shfl_down_sync(0xffffffffu, sR, o);
                        sC += __shfl_down_sync(0xffffffffu, sC, o);
                    }
                    if (lane == 0) { prc_s[0][lr] = sR; prc_s[1][lr] = sC; }
                }
            }
            __threadfence_block();
            if (lane == 0) flP[sw] = t;
        } else if (mv_active) {
            // ---- dot warps: U batches 0-15; R,C batches 0-13 only ----
            const float h_old = hin[myrow];     // fp32 state read, issued early
            unsigned long long au = 0ull, ar = 0ull, ac = 0ull;

            uint4 wu0 = pu[lane], wr0 = pr[lane], wc0 = pc[lane];  // pre-wait
            wait_flags(flA, t);
            #pragma unroll
            for (int k = 0; k < 16; ++k) {
                const int j = lane + 32 * k;   // compile-time offset after unroll
                uint4 nu, nr, nc;
                if (k < 15) { nu = pu[j + 32]; }
                if (k < 13) { nr = pr[j + 32]; nc = pc[j + 32]; }
                if (k == 8) wait_flags(flB, t);
                uint4 hh = h2s[j];             // 8 fp16 h, permuted-packed
                float2 fu = dot8h(wu0, hh);
                fadd2(au, fu.x, fu.y);
                if (k < 14) {
                    float2 fr = dot8h(wr0, hh);
                    float2 fc = dot8h(wc0, hh);
                    fadd2(ar, fr.x, fr.y);
                    fadd2(ac, fc.x, fc.y);
                }
                if (k < 15) { wu0 = nu; }
                if (k < 13) { wr0 = nr; wc0 = nc; }
            }

            float su = hsum2(au), sr = hsum2(ar), sc = hsum2(ac);
            #pragma unroll
            for (int o = 16; o; o >>= 1) {
                su += __shfl_down_sync(0xffffffffu, su, o);
                sr += __shfl_down_sync(0xffffffffu, sr, o);
                sc += __shfl_down_sync(0xffffffffu, sc, o);
            }

            // decentralized gate: lane 0 updates its own row (fp32 chain)
            if (lane == 0) {
                volatile int* fp = &flP[warp / 7];
                while (*fp < t) { }            // stager partials ready
                sr += prc_s[0][warp];
                sc += prc_s[1][warp];
                volatile int* fx = &flX;
                while (*fx < t) { }            // long since set
                const float x = x_s;
                const float u  = sigmoidf_fast(gc_s[0][warp] * x + su + gc_s[1][warp]);
                const float r  = sigmoidf_fast(gc_s[2][warp] * x + sr + gc_s[3][warp]);
                const float hh = tanhf(gc_s[4][warp] * x + r * sc + gc_s[5][warp]);
                const float hn = h_old + u * (hh - h_old);
                hout[myrow] = hn;
                if (need_y) red_s[warp] = gc_s[6][warp] * hn;
            }
        }

        // y partial reduction only on the last horizon+1 steps
        if (need_y) {
            __syncthreads();
            if (warp == 0) {
                float yv = (lane < nrows) ? red_s[lane] : 0.f;
                #pragma unroll
                for (int o = 16; o; o >>= 1)
                    yv += __shfl_down_sync(0xffffffffu, yv, o);
                if (lane == 0) g_vhp[t - (T_TRAIN - 1)][b] = yv;
            }
        }

        grid_barrier(phase, G);
    }

    // emit predictions (deterministic final reduction)
    if (b == 0 && tid < horizon) {
        const float* p = g_vhp[tid + 1];
        float s = 0.f;
        for (int i = 0; i < G; ++i) s += p[i];
        out[tid] = s + c0;
    }
}

// ---------------- launch ----------------------------------------------------
extern "C" void kernel_launch(void* const* d_in, const int* in_sizes, int n_in,
                              void* d_out, int out_size)
{
    (void)in_sizes; (void)n_in;
    const float* x_seq = (const float*)d_in[0];
    // d_in[1] is the scalar 'horizon' (int32); we use out_size instead.
    const float* uwx = (const float*)d_in[2];
    const float* uWh = (const float*)d_in[3];
    const float* ub  = (const float*)d_in[4];
    const float* rwx = (const float*)d_in[5];
    const float* rWh = (const float*)d_in[6];
    const float* rb  = (const float*)d_in[7];
    const float* wx  = (const float*)d_in[8];
    const float* Wh  = (const float*)d_in[9];
    const float* bb  = (const float*)d_in[10];
    const float* v   = (const float*)d_in[11];
    const float* cc  = (const float*)d_in[12];

    int horizon = out_size;
    if (horizon > HMAX) horizon = HMAX;

    // reset persistent state (graph-capturable, deterministic per replay)
    void* p;
    cudaGetSymbolAddress(&p, g_h);     cudaMemsetAsync(p, 0, sizeof(float) * 2 * H);
    cudaGetSymbolAddress(&p, g_count); cudaMemsetAsync(p, 0, sizeof(unsigned));
    cudaGetSymbolAddress(&p, g_phase); cudaMemsetAsync(p, 0, sizeof(unsigned));

    // fp32 -> fp16 permuted weight conversion
    {
        const int total = H * ROW_U4;
        convert_w<<<(total + 255) / 256, 256>>>(uWh, rWh, Wh);
    }

    // dyn-smem: try 27-row cache, then 26, then none (same decision every call)
    const int base = H2_U4 * (int)sizeof(uint4);      // 8 KB packed fp16 h
    int ncache = NCACHE;
    int dyn    = base + NCACHE * ROW_U4 * (int)sizeof(uint4);
    cudaError_t e = cudaFuncSetAttribute(gru_persistent,
                                         cudaFuncAttributeMaxDynamicSharedMemorySize,
                                         dyn);
    if (e != cudaSuccess) {
        (void)cudaGetLastError();
        ncache = 26;
        dyn    = base + 26 * ROW_U4 * (int)sizeof(uint4);
        e = cudaFuncSetAttribute(gru_persistent,
                                 cudaFuncAttributeMaxDynamicSharedMemorySize,
                                 dyn);
        if (e != cudaSuccess) {
            (void)cudaGetLastError();
            ncache = 0;
            dyn    = base;
        }
    }

    gru_persistent<<<GRID, BLOCK, dyn>>>(x_seq,
                                         uwx, ub,
                                         rwx, rb,
                                         wx,  bb,
                                         v,   cc,
                                         (float*)d_out, horizon, ncache);
}

// round 15
// speedup vs baseline: 1.2815x; 1.2815x over previous
#include <cuda_runtime.h>
#include <cuda_fp16.h>
#include <cstdint>

#define H        4096
#define T_TRAIN  2048
#define GRID     148
#define BLOCK    1024         // 28 dot warps + 4 stager warps
#define DOTW     28
#define HMAX     64
#define NCACHE   27           // U-matrix rows cached in SMEM per CTA (big path)
#define ROW_U4   512          // uint4 per weight row (4096 halves = 8 KB)
#define H2_U4    512          // uint4 of packed fp16 h (4096 halves = 8 KB)

// ---------------- persistent device state ----------------------------------
__device__ __half   g_wu[(size_t)H * H];   // fp16 weights, PERMUTED layout:
__device__ __half   g_wr[(size_t)H * H];   // chunk j = cols {4j..4j+3, 2048+4j..2048+4j+3}
__device__ __half   g_wc[(size_t)H * H];
__device__ float    g_h[2][H];             // fp32 hidden-state chain (accuracy-critical)
__device__ float    g_vhp[HMAX + 1][GRID];
__device__ unsigned g_count;               // centralized barrier (R8-proven)
__device__ unsigned g_phase;

// ---------------- fp32 -> fp16 conversion with column permutation -----------
__global__ void convert_w(const float* __restrict__ u,
                          const float* __restrict__ r,
                          const float* __restrict__ c)
{
    const int total = H * ROW_U4;
    int idx = blockIdx.x * blockDim.x + threadIdx.x;
    if (idx >= total) return;
    const int row = idx >> 9;
    const int j   = idx & 511;
    const int i0  = row * (H / 4) + j;        // float4 index of cols 4j..4j+3
    const int i1  = i0 + 512;                 // float4 index of cols 2048+4j..+3

    #define CVT_ONE(SRC, DST)                                           \
    {                                                                   \
        float4 a = ((const float4*)SRC)[i0];                            \
        float4 b = ((const float4*)SRC)[i1];                            \
        uint4 o;                                                        \
        __half2 t;                                                      \
        t = __floats2half2_rn(a.x, a.y); o.x = *(unsigned*)&t;          \
        t = __floats2half2_rn(a.z, a.w); o.y = *(unsigned*)&t;          \
        t = __floats2half2_rn(b.x, b.y); o.z = *(unsigned*)&t;          \
        t = __floats2half2_rn(b.z, b.w); o.w = *(unsigned*)&t;          \
        ((uint4*)DST)[idx] = o;                                         \
    }
    CVT_ONE(u, g_wu)
    CVT_ONE(r, g_wr)
    CVT_ONE(c, g_wc)
    #undef CVT_ONE
}

// ---------------- grid-wide barrier (R8-proven centralized version) ----------
__device__ __forceinline__ void grid_barrier(unsigned &local_phase, int G) {
    __threadfence();
    __syncthreads();
    if (threadIdx.x == 0) {
        unsigned target = local_phase + 1;
        unsigned arrived = atomicAdd(&g_count, 1u) + 1;
        if (arrived == (unsigned)G) {
            atomicExch(&g_count, 0u);
            __threadfence();
            atomicAdd(&g_phase, 1u);
        } else {
            volatile unsigned* ph = &g_phase;
            while (*ph < target) { }
        }
    }
    local_phase++;
    __syncthreads();
    __threadfence();
}

__device__ __forceinline__ float sigmoidf_fast(float z) {
    return 1.0f / (1.0f + __expf(-z));
}

// packed f32x2 add: acc(lo,hi) += (x0,x1); acc carried as u64
__device__ __forceinline__ void fadd2(unsigned long long& acc, float x0, float x1)
{
    unsigned long long a;
    asm("mov.b64 %0, {%1, %2};" : "=l"(a) : "f"(x0), "f"(x1));
    asm("add.rn.f32x2 %0, %1, %2;" : "=l"(acc) : "l"(acc), "l"(a));
}

__device__ __forceinline__ float hsum2(unsigned long long acc) {
    float lo, hi;
    asm("mov.b64 {%0, %1}, %2;" : "=f"(lo), "=f"(hi) : "l"(acc));
    return lo + hi;
}

__device__ __forceinline__ __half2 u2h2(unsigned v) { return *(__half2*)&v; }

// 8-element packed-half partial dot: (w uint4) . (h uint4) -> float2
__device__ __forceinline__ float2 dot8h(uint4 w, uint4 h)
{
    __half2 p = __hmul2(u2h2(w.x), u2h2(h.x));
    p = __hfma2(u2h2(w.y), u2h2(h.y), p);
    p = __hfma2(u2h2(w.z), u2h2(h.z), p);
    p = __hfma2(u2h2(w.w), u2h2(h.w), p);
    return __half22float2(p);
}

// spin on 4 per-stager-warp step flags (values are monotone step numbers)
__device__ __forceinline__ void wait_flags(volatile int* f, int t) {
    while (f[0] < t || f[1] < t || f[2] < t || f[3] < t) { }
}

// ---------------- persistent GRU kernel -------------------------------------
__global__ void __launch_bounds__(BLOCK, 1)
gru_persistent(const float* __restrict__ x_seq,
               const float* __restrict__ uwx, const float* __restrict__ ub,
               const float* __restrict__ rwx, const float* __restrict__ rb,
               const float* __restrict__ wx,  const float* __restrict__ bb,
               const float* __restrict__ v,   const float* __restrict__ cc,
               float* __restrict__ out, int horizon, int ncache)
{
    extern __shared__ char smem[];
    uint4* h2s = (uint4*)smem;                          // 8 KB packed fp16 h
    uint4* ws  = (uint4*)(smem + H2_U4 * sizeof(uint4)); // ncache rows of U

    __shared__ float red_s[32];
    __shared__ float gc_s[7][DOTW];      // gate constants per owned row
    __shared__ float x_s;
    __shared__ int   flA[4], flB[4];     // per-stager-warp flags
    __shared__ int   flX;                // x-ready flag

    const int tid  = threadIdx.x;
    const int b    = blockIdx.x;
    const int G    = gridDim.x;
    const int warp = tid >> 5;
    const int lane = tid & 31;

    const int r0 = (int)(((long long)b       * H) / G);
    const int r1 = (int)(((long long)(b + 1) * H) / G);
    const int nrows = r1 - r0;   // 27 or 28 (<= DOTW)

    if (tid < 4) { flA[tid] = -1; flB[tid] = -1; }
    if (tid == 4) flX = -1;
    if (tid < 32) red_s[tid] = 0.f;
    // stage gate constants into SMEM (row r0+i -> column i)
    if (tid < nrows) {
        const int row = r0 + tid;
        gc_s[0][tid] = uwx[row]; gc_s[1][tid] = ub[row];
        gc_s[2][tid] = rwx[row]; gc_s[3][tid] = rb[row];
        gc_s[4][tid] = wx[row];  gc_s[5][tid] = bb[row];
        gc_s[6][tid] = v[row];
    }

    // prologue: pin first `ncache` U-rows of this CTA into SMEM
    {
        const uint4* src = ((const uint4*)g_wu) + (size_t)r0 * ROW_U4;
        const int n = ncache * ROW_U4;
        for (int i = tid; i < n; i += BLOCK) ws[i] = src[i];
    }

    // matvec row pointers (warp w owns row r0+w for all three matrices)
    const bool mv_active = (warp < nrows);
    const int  myrow = r0 + warp;
    const uint4* pu = nullptr; const uint4* pr = nullptr; const uint4* pc = nullptr;
    if (mv_active) {
        const size_t off = (size_t)myrow * ROW_U4;
        pu = (warp < ncache) ? (ws + (size_t)warp * ROW_U4)
                             : (((const uint4*)g_wu) + off);
        pr = ((const uint4*)g_wr) + off;
        pc = ((const uint4*)g_wc) + off;
    }

    const float c0 = cc[0];
    unsigned phase = 0;
    const int total_steps = T_TRAIN + horizon;
    __syncthreads();   // flags/constants/ws visible to all warps

    // cross-step pipelined lead weights (batch 0 of step 0), issued once here;
    // thereafter re-issued at the END of each step so the ~L2 latency hides
    // behind the grid barrier.
    uint4 wu0 = {0,0,0,0}, wr0 = {0,0,0,0}, wc0 = {0,0,0,0};
    if (warp < DOTW && mv_active) {
        wu0 = pu[lane]; wr0 = pr[lane]; wc0 = pc[lane];
    }

    for (int t = 0; t < total_steps; ++t) {
        const int par = t & 1;
        const float* hin  = g_h[par];
        float*       hout = g_h[par ^ 1];
        const bool need_y = (t >= T_TRAIN - 1);

        if (warp >= DOTW) {
            // ---- stager warps: convert fp32 h -> packed-permuted fp16 ----
            const int sw  = warp - DOTW;        // 0..3
            const int sid = tid - DOTW * 32;    // 0..127

            // warp 31: publish x FIRST so dot warps never wait at the tail
            if (warp == 31) {
                if (t < T_TRAIN) {
                    if (lane == 0) {
                        x_s = x_seq[t];
                        __threadfence_block();
                        flX = t;
                    }
                } else {
                    const float* p = g_vhp[t - T_TRAIN];
                    float s = 0.f;
                    for (int i = lane; i < G; i += 32) s += p[i];
                    #pragma unroll
                    for (int o = 16; o; o >>= 1)
                        s += __shfl_down_sync(0xffffffffu, s, o);
                    if (lane == 0) {
                        x_s = s + c0;
                        __threadfence_block();
                        flX = t;
                    }
                }
            }

            const float4* src = (const float4*)hin;
            // chunk A: j in [0,256)  (dot batches k<8)
            #pragma unroll
            for (int i = sid; i < 256; i += 128) {
                float4 a = src[i];
                float4 bq = src[512 + i];
                uint4 o; __half2 tt;
                tt = __floats2half2_rn(a.x,  a.y);  o.x = *(unsigned*)&tt;
                tt = __floats2half2_rn(a.z,  a.w);  o.y = *(unsigned*)&tt;
                tt = __floats2half2_rn(bq.x, bq.y); o.z = *(unsigned*)&tt;
                tt = __floats2half2_rn(bq.z, bq.w); o.w = *(unsigned*)&tt;
                h2s[i] = o;
            }
            __syncwarp();
            __threadfence_block();
            if (lane == 0) flA[sw] = t;
            // chunk B: j in [256,512)  (dot batches k>=8)
            #pragma unroll
            for (int i = sid + 256; i < 512; i += 128) {
                float4 a = src[i];
                float4 bq = src[512 + i];
                uint4 o; __half2 tt;
                tt = __floats2half2_rn(a.x,  a.y);  o.x = *(unsigned*)&tt;
                tt = __floats2half2_rn(a.z,  a.w);  o.y = *(unsigned*)&tt;
                tt = __floats2half2_rn(bq.x, bq.y); o.z = *(unsigned*)&tt;
                tt = __floats2half2_rn(bq.z, bq.w); o.w = *(unsigned*)&tt;
                h2s[i] = o;
            }
            __syncwarp();
            __threadfence_block();
            if (lane == 0) flB[sw] = t;
        } else if (mv_active) {
            // ---- dot warps: merged 16-batch loop, packed-half partials;
            //      lead weights (batch 0) were loaded BEFORE the barrier ----
            const float h_old = hin[myrow];     // fp32 state read, issued early
            unsigned long long au = 0ull, ar = 0ull, ac = 0ull;

            wait_flags(flA, t);
            #pragma unroll
            for (int k = 0; k < 16; ++k) {
                const int j = lane + 32 * k;   // compile-time offset after unroll
                uint4 nu, nr, nc;
                if (k < 15) {                  // in-step prefetch (folds away)
                    nu = pu[j + 32]; nr = pr[j + 32]; nc = pc[j + 32];
                } else {                       // cross-step prefetch: batch 0 of t+1
                    nu = pu[lane]; nr = pr[lane]; nc = pc[lane];
                }
                if (k == 8) wait_flags(flB, t);   // batch-8 weights already in flight
                uint4 hh = h2s[j];             // 8 fp16 h, permuted-packed
                float2 fu = dot8h(wu0, hh);
                float2 fr = dot8h(wr0, hh);
                float2 fc = dot8h(wc0, hh);
                fadd2(au, fu.x, fu.y);
                fadd2(ar, fr.x, fr.y);
                fadd2(ac, fc.x, fc.y);
                wu0 = nu; wr0 = nr; wc0 = nc;  // after k=15: holds t+1 batch 0
            }

            float su = hsum2(au), sr = hsum2(ar), sc = hsum2(ac);
            #pragma unroll
            for (int o = 16; o; o >>= 1) {
                su += __shfl_down_sync(0xffffffffu, su, o);
                sr += __shfl_down_sync(0xffffffffu, sr, o);
                sc += __shfl_down_sync(0xffffffffu, sc, o);
            }

            // decentralized gate: lane 0 updates its own row (fp32 chain)
            if (lane == 0) {
                volatile int* fx = &flX;
                while (*fx < t) { }            // long since set
                const float x = x_s;
                const float u  = sigmoidf_fast(gc_s[0][warp] * x + su + gc_s[1][warp]);
                const float r  = sigmoidf_fast(gc_s[2][warp] * x + sr + gc_s[3][warp]);
                const float hh = tanhf(gc_s[4][warp] * x + r * sc + gc_s[5][warp]);
                const float hn = h_old + u * (hh - h_old);
                hout[myrow] = hn;
                if (need_y) red_s[warp] = gc_s[6][warp] * hn;
            }
        }

        // y partial reduction only on the last horizon+1 steps
        if (need_y) {
            __syncthreads();
            if (warp == 0) {
                float yv = (lane < nrows) ? red_s[lane] : 0.f;
                #pragma unroll
                for (int o = 16; o; o >>= 1)
                    yv += __shfl_down_sync(0xffffffffu, yv, o);
                if (lane == 0) g_vhp[t - (T_TRAIN - 1)][b] = yv;
            }
        }

        grid_barrier(phase, G);   // next-step lead weights in flight during this
    }

    // emit predictions (deterministic final reduction)
    if (b == 0 && tid < horizon) {
        const float* p = g_vhp[tid + 1];
        float s = 0.f;
        for (int i = 0; i < G; ++i) s += p[i];
        out[tid] = s + c0;
    }
}

// ---------------- launch ----------------------------------------------------
extern "C" void kernel_launch(void* const* d_in, const int* in_sizes, int n_in,
                              void* d_out, int out_size)
{
    (void)in_sizes; (void)n_in;
    const float* x_seq = (const float*)d_in[0];
    // d_in[1] is the scalar 'horizon' (int32); we use out_size instead.
    const float* uwx = (const float*)d_in[2];
    const float* uWh = (const float*)d_in[3];
    const float* ub  = (const float*)d_in[4];
    const float* rwx = (const float*)d_in[5];
    const float* rWh = (const float*)d_in[6];
    const float* rb  = (const float*)d_in[7];
    const float* wx  = (const float*)d_in[8];
    const float* Wh  = (const float*)d_in[9];
    const float* bb  = (const float*)d_in[10];
    const float* v   = (const float*)d_in[11];
    const float* cc  = (const float*)d_in[12];

    int horizon = out_size;
    if (horizon > HMAX) horizon = HMAX;

    // reset persistent state (graph-capturable, deterministic per replay)
    void* p;
    cudaGetSymbolAddress(&p, g_h);     cudaMemsetAsync(p, 0, sizeof(float) * 2 * H);
    cudaGetSymbolAddress(&p, g_count); cudaMemsetAsync(p, 0, sizeof(unsigned));
    cudaGetSymbolAddress(&p, g_phase); cudaMemsetAsync(p, 0, sizeof(unsigned));

    // fp32 -> fp16 permuted weight conversion
    {
        const int total = H * ROW_U4;
        convert_w<<<(total + 255) / 256, 256>>>(uWh, rWh, Wh);
    }

    // dyn-smem: try 27-row cache, then 26, then none (same decision every call)
    const int base = H2_U4 * (int)sizeof(uint4);      // 8 KB packed fp16 h
    int ncache = NCACHE;
    int dyn    = base + NCACHE * ROW_U4 * (int)sizeof(uint4);
    cudaError_t e = cudaFuncSetAttribute(gru_persistent,
                                         cudaFuncAttributeMaxDynamicSharedMemorySize,
                                         dyn);
    if (e != cudaSuccess) {
        (void)cudaGetLastError();
        ncache = 26;
        dyn    = base + 26 * ROW_U4 * (int)sizeof(uint4);
        e = cudaFuncSetAttribute(gru_persistent,
                                 cudaFuncAttributeMaxDynamicSharedMemorySize,
                                 dyn);
        if (e != cudaSuccess) {
            (void)cudaGetLastError();
            ncache = 0;
            dyn    = base;
        }
    }

    gru_persistent<<<GRID, BLOCK, dyn>>>(x_seq,
                                         uwx, ub,
                                         rwx, rb,
                                         wx,  bb,
                                         v,   cc,
                                         (float*)d_out, horizon, ncache);
}

// round 16
// speedup vs baseline: 1.3041x; 1.0176x over previous
#include <cuda_runtime.h>
#include <cuda_fp16.h>
#include <cstdint>

#define H        4096
#define T_TRAIN  2048
#define GRID     148
#define BLOCK    1024         // 28 dot warps + 4 stager warps
#define DOTW     28
#define HMAX     64
#define NCACHE   27           // U-matrix rows cached in SMEM per CTA (big path)
#define ROW_U4   512          // uint4 per weight row (4096 halves = 8 KB)
#define H2_U4    512          // uint4 of packed fp16 h (4096 halves = 8 KB)

// ---------------- persistent device state ----------------------------------
__device__ __half   g_wu[(size_t)H * H];   // fp16 weights, PERMUTED layout:
__device__ __half   g_wr[(size_t)H * H];   // chunk j = cols {4j..4j+3, 2048+4j..2048+4j+3}
__device__ __half   g_wc[(size_t)H * H];
__device__ float    g_h[2][H];             // fp32 hidden-state chain (accuracy-critical)
__device__ __half   g_h16[2][H];           // packed-PERMUTED fp16 mirror of g_h
__device__ float    g_vhp[HMAX + 1][GRID];
__device__ unsigned g_count;               // centralized barrier (R8-proven)
__device__ unsigned g_phase;

// ---------------- fp32 -> fp16 conversion with column permutation -----------
__global__ void convert_w(const float* __restrict__ u,
                          const float* __restrict__ r,
                          const float* __restrict__ c)
{
    const int total = H * ROW_U4;
    int idx = blockIdx.x * blockDim.x + threadIdx.x;
    if (idx >= total) return;
    const int row = idx >> 9;
    const int j   = idx & 511;
    const int i0  = row * (H / 4) + j;        // float4 index of cols 4j..4j+3
    const int i1  = i0 + 512;                 // float4 index of cols 2048+4j..+3

    #define CVT_ONE(SRC, DST)                                           \
    {                                                                   \
        float4 a = ((const float4*)SRC)[i0];                            \
        float4 b = ((const float4*)SRC)[i1];                            \
        uint4 o;                                                        \
        __half2 t;                                                      \
        t = __floats2half2_rn(a.x, a.y); o.x = *(unsigned*)&t;          \
        t = __floats2half2_rn(a.z, a.w); o.y = *(unsigned*)&t;          \
        t = __floats2half2_rn(b.x, b.y); o.z = *(unsigned*)&t;          \
        t = __floats2half2_rn(b.z, b.w); o.w = *(unsigned*)&t;          \
        ((uint4*)DST)[idx] = o;                                         \
    }
    CVT_ONE(u, g_wu)
    CVT_ONE(r, g_wr)
    CVT_ONE(c, g_wc)
    #undef CVT_ONE
}

// ---------------- grid-wide barrier (R8-proven centralized version) ----------
__device__ __forceinline__ void grid_barrier(unsigned &local_phase, int G) {
    __threadfence();
    __syncthreads();
    if (threadIdx.x == 0) {
        unsigned target = local_phase + 1;
        unsigned arrived = atomicAdd(&g_count, 1u) + 1;
        if (arrived == (unsigned)G) {
            atomicExch(&g_count, 0u);
            __threadfence();
            atomicAdd(&g_phase, 1u);
        } else {
            volatile unsigned* ph = &g_phase;
            while (*ph < target) { }
        }
    }
    local_phase++;
    __syncthreads();
    __threadfence();
}

__device__ __forceinline__ float sigmoidf_fast(float z) {
    return 1.0f / (1.0f + __expf(-z));
}

// packed f32x2 add: acc(lo,hi) += (x0,x1); acc carried as u64
__device__ __forceinline__ void fadd2(unsigned long long& acc, float x0, float x1)
{
    unsigned long long a;
    asm("mov.b64 %0, {%1, %2};" : "=l"(a) : "f"(x0), "f"(x1));
    asm("add.rn.f32x2 %0, %1, %2;" : "=l"(acc) : "l"(acc), "l"(a));
}

__device__ __forceinline__ float hsum2(unsigned long long acc) {
    float lo, hi;
    asm("mov.b64 {%0, %1}, %2;" : "=f"(lo), "=f"(hi) : "l"(acc));
    return lo + hi;
}

__device__ __forceinline__ __half2 u2h2(unsigned v) { return *(__half2*)&v; }

// 8-element packed-half partial dot: (w uint4) . (h uint4) -> float2
__device__ __forceinline__ float2 dot8h(uint4 w, uint4 h)
{
    __half2 p = __hmul2(u2h2(w.x), u2h2(h.x));
    p = __hfma2(u2h2(w.y), u2h2(h.y), p);
    p = __hfma2(u2h2(w.z), u2h2(h.z), p);
    p = __hfma2(u2h2(w.w), u2h2(h.w), p);
    return __half22float2(p);
}

// spin on 4 per-stager-warp step flags (values are monotone step numbers)
__device__ __forceinline__ void wait_flags(volatile int* f, int t) {
    while (f[0] < t || f[1] < t || f[2] < t || f[3] < t) { }
}

// ---------------- persistent GRU kernel -------------------------------------
__global__ void __launch_bounds__(BLOCK, 1)
gru_persistent(const float* __restrict__ x_seq,
               const float* __restrict__ uwx, const float* __restrict__ ub,
               const float* __restrict__ rwx, const float* __restrict__ rb,
               const float* __restrict__ wx,  const float* __restrict__ bb,
               const float* __restrict__ v,   const float* __restrict__ cc,
               float* __restrict__ out, int horizon, int ncache)
{
    extern __shared__ char smem[];
    uint4* h2s = (uint4*)smem;                          // 8 KB packed fp16 h
    uint4* ws  = (uint4*)(smem + H2_U4 * sizeof(uint4)); // ncache rows of U

    __shared__ float red_s[32];
    __shared__ float gc_s[7][DOTW];      // gate constants per owned row
    __shared__ float x_s;
    __shared__ int   flA[4], flB[4];     // per-stager-warp flags
    __shared__ int   flX;                // x-ready flag

    const int tid  = threadIdx.x;
    const int b    = blockIdx.x;
    const int G    = gridDim.x;
    const int warp = tid >> 5;
    const int lane = tid & 31;

    const int r0 = (int)(((long long)b       * H) / G);
    const int r1 = (int)(((long long)(b + 1) * H) / G);
    const int nrows = r1 - r0;   // 27 or 28 (<= DOTW)

    if (tid < 4) { flA[tid] = -1; flB[tid] = -1; }
    if (tid == 4) flX = -1;
    if (tid < 32) red_s[tid] = 0.f;
    // stage gate constants into SMEM (row r0+i -> column i)
    if (tid < nrows) {
        const int row = r0 + tid;
        gc_s[0][tid] = uwx[row]; gc_s[1][tid] = ub[row];
        gc_s[2][tid] = rwx[row]; gc_s[3][tid] = rb[row];
        gc_s[4][tid] = wx[row];  gc_s[5][tid] = bb[row];
        gc_s[6][tid] = v[row];
    }

    // prologue: pin first `ncache` U-rows of this CTA into SMEM
    {
        const uint4* src = ((const uint4*)g_wu) + (size_t)r0 * ROW_U4;
        const int n = ncache * ROW_U4;
        for (int i = tid; i < n; i += BLOCK) ws[i] = src[i];
    }

    // matvec row pointers (warp w owns row r0+w for all three matrices)
    const bool mv_active = (warp < nrows);
    const int  myrow = r0 + warp;
    const uint4* pu = nullptr; const uint4* pr = nullptr; const uint4* pc = nullptr;
    if (mv_active) {
        const size_t off = (size_t)myrow * ROW_U4;
        pu = (warp < ncache) ? (ws + (size_t)warp * ROW_U4)
                             : (((const uint4*)g_wu) + off);
        pr = ((const uint4*)g_wr) + off;
        pc = ((const uint4*)g_wc) + off;
    }

    // permuted fp16 write index for this warp's row
    const int h16_idx = (myrow < 2048) ? ((myrow >> 2) * 8 + (myrow & 3))
                                       : (((myrow - 2048) >> 2) * 8 + 4 + (myrow & 3));

    const float c0 = cc[0];
    unsigned phase = 0;
    const int total_steps = T_TRAIN + horizon;
    __syncthreads();   // flags/constants/ws visible to all warps

    // cross-step pipelined lead weights (batch 0 of step 0)
    uint4 wu0 = {0,0,0,0}, wr0 = {0,0,0,0}, wc0 = {0,0,0,0};
    if (warp < DOTW && mv_active) {
        wu0 = pu[lane]; wr0 = pr[lane]; wc0 = pc[lane];
    }

    for (int t = 0; t < total_steps; ++t) {
        const int par = t & 1;
        const float* hin  = g_h[par];
        float*       hout = g_h[par ^ 1];
        const bool need_y = (t >= T_TRAIN - 1);

        if (warp >= DOTW) {
            // ---- stager warps: verbatim 8 KB copy of packed fp16 h ----
            const int sw  = warp - DOTW;        // 0..3
            const int sid = tid - DOTW * 32;    // 0..127

            // warp 31: publish x FIRST so dot warps never wait at the tail
            if (warp == 31) {
                if (t < T_TRAIN) {
                    if (lane == 0) {
                        x_s = x_seq[t];
                        __threadfence_block();
                        flX = t;
                    }
                } else {
                    const float* p = g_vhp[t - T_TRAIN];
                    float s = 0.f;
                    for (int i = lane; i < G; i += 32) s += p[i];
                    #pragma unroll
                    for (int o = 16; o; o >>= 1)
                        s += __shfl_down_sync(0xffffffffu, s, o);
                    if (lane == 0) {
                        x_s = s + c0;
                        __threadfence_block();
                        flX = t;
                    }
                }
            }

            const uint4* src16 = (const uint4*)g_h16[par];
            // chunk A: uint4 [0,256)  (dot batches k<8)
            #pragma unroll
            for (int i = sid; i < 256; i += 128) h2s[i] = src16[i];
            __syncwarp();
            __threadfence_block();
            if (lane == 0) flA[sw] = t;
            // chunk B: uint4 [256,512)  (dot batches k>=8)
            #pragma unroll
            for (int i = sid + 256; i < 512; i += 128) h2s[i] = src16[i];
            __syncwarp();
            __threadfence_block();
            if (lane == 0) flB[sw] = t;
        } else if (mv_active) {
            // ---- dot warps: merged 16-batch loop, packed-half partials ----
            const float h_old = hin[myrow];     // fp32 state read, issued early
            unsigned long long au = 0ull, ar = 0ull, ac = 0ull;

            wait_flags(flA, t);
            #pragma unroll
            for (int k = 0; k < 16; ++k) {
                const int j = lane + 32 * k;   // compile-time offset after unroll
                uint4 nu, nr, nc;
                if (k < 15) {                  // in-step prefetch (folds away)
                    nu = pu[j + 32]; nr = pr[j + 32]; nc = pc[j + 32];
                } else {                       // cross-step prefetch: batch 0 of t+1
                    nu = pu[lane]; nr = pr[lane]; nc = pc[lane];
                }
                if (k == 8) wait_flags(flB, t);
                uint4 hh = h2s[j];             // 8 fp16 h, permuted-packed
                float2 fu = dot8h(wu0, hh);
                float2 fr = dot8h(wr0, hh);
                float2 fc = dot8h(wc0, hh);
                fadd2(au, fu.x, fu.y);
                fadd2(ar, fr.x, fr.y);
                fadd2(ac, fc.x, fc.y);
                wu0 = nu; wr0 = nr; wc0 = nc;  // after k=15: holds t+1 batch 0
            }

            float su = hsum2(au), sr = hsum2(ar), sc = hsum2(ac);
            #pragma unroll
            for (int o = 16; o; o >>= 1) {
                su += __shfl_down_sync(0xffffffffu, su, o);
                sr += __shfl_down_sync(0xffffffffu, sr, o);
                sc += __shfl_down_sync(0xffffffffu, sc, o);
            }

            // decentralized gate: lane 0 updates its own row (fp32 chain +
            // packed-permuted fp16 mirror for next step's staging)
            if (lane == 0) {
                volatile int* fx = &flX;
                while (*fx < t) { }            // long since set
                const float x = x_s;
                const float u  = sigmoidf_fast(gc_s[0][warp] * x + su + gc_s[1][warp]);
                const float r  = sigmoidf_fast(gc_s[2][warp] * x + sr + gc_s[3][warp]);
                const float hh = tanhf(gc_s[4][warp] * x + r * sc + gc_s[5][warp]);
                const float hn = h_old + u * (hh - h_old);
                hout[myrow] = hn;
                g_h16[par ^ 1][h16_idx] = __float2half_rn(hn);
                if (need_y) red_s[warp] = gc_s[6][warp] * hn;
            }
        }

        // y partial reduction only on the last horizon+1 steps
        if (need_y) {
            __syncthreads();
            if (warp == 0) {
                float yv = (lane < nrows) ? red_s[lane] : 0.f;
                #pragma unroll
                for (int o = 16; o; o >>= 1)
                    yv += __shfl_down_sync(0xffffffffu, yv, o);
                if (lane == 0) g_vhp[t - (T_TRAIN - 1)][b] = yv;
            }
        }

        grid_barrier(phase, G);   // next-step lead weights in flight during this
    }

    // emit predictions (deterministic final reduction)
    if (b == 0 && tid < horizon) {
        const float* p = g_vhp[tid + 1];
        float s = 0.f;
        for (int i = 0; i < G; ++i) s += p[i];
        out[tid] = s + c0;
    }
}

// ---------------- launch ----------------------------------------------------
extern "C" void kernel_launch(void* const* d_in, const int* in_sizes, int n_in,
                              void* d_out, int out_size)
{
    (void)in_sizes; (void)n_in;
    const float* x_seq = (const float*)d_in[0];
    // d_in[1] is the scalar 'horizon' (int32); we use out_size instead.
    const float* uwx = (const float*)d_in[2];
    const float* uWh = (const float*)d_in[3];
    const float* ub  = (const float*)d_in[4];
    const float* rwx = (const float*)d_in[5];
    const float* rWh = (const float*)d_in[6];
    const float* rb  = (const float*)d_in[7];
    const float* wx  = (const float*)d_in[8];
    const float* Wh  = (const float*)d_in[9];
    const float* bb  = (const float*)d_in[10];
    const float* v   = (const float*)d_in[11];
    const float* cc  = (const float*)d_in[12];

    int horizon = out_size;
    if (horizon > HMAX) horizon = HMAX;

    // reset persistent state (graph-capturable, deterministic per replay)
    void* p;
    cudaGetSymbolAddress(&p, g_h);     cudaMemsetAsync(p, 0, sizeof(float) * 2 * H);
    cudaGetSymbolAddress(&p, g_h16);   cudaMemsetAsync(p, 0, sizeof(__half) * 2 * H);
    cudaGetSymbolAddress(&p, g_count); cudaMemsetAsync(p, 0, sizeof(unsigned));
    cudaGetSymbolAddress(&p, g_phase); cudaMemsetAsync(p, 0, sizeof(unsigned));

    // fp32 -> fp16 permuted weight conversion
    {
        const int total = H * ROW_U4;
        convert_w<<<(total + 255) / 256, 256>>>(uWh, rWh, Wh);
    }

    // dyn-smem: try 27-row cache, then 26, then none (same decision every call)
    const int base = H2_U4 * (int)sizeof(uint4);      // 8 KB packed fp16 h
    int ncache = NCACHE;
    int dyn    = base + NCACHE * ROW_U4 * (int)sizeof(uint4);
    cudaError_t e = cudaFuncSetAttribute(gru_persistent,
                                         cudaFuncAttributeMaxDynamicSharedMemorySize,
                                         dyn);
    if (e != cudaSuccess) {
        (void)cudaGetLastError();
        ncache = 26;
        dyn    = base + 26 * ROW_U4 * (int)sizeof(uint4);
        e = cudaFuncSetAttribute(gru_persistent,
                                 cudaFuncAttributeMaxDynamicSharedMemorySize,
                                 dyn);
        if (e != cudaSuccess) {
            (void)cudaGetLastError();
            ncache = 0;
            dyn    = base;
        }
    }

    gru_persistent<<<GRID, BLOCK, dyn>>>(x_seq,
                                         uwx, ub,
                                         rwx, rb,
                                         wx,  bb,
                                         v,   cc,
                                         (float*)d_out, horizon, ncache);
}

// round 17
// speedup vs baseline: 1.3125x; 1.0065x over previous
#include <cuda_runtime.h>
#include <cuda_fp16.h>
#include <cstdint>

#define H        4096
#define T_TRAIN  2048
#define GRID     148
#define BLOCK    1024         // 28 dot warps + 4 stager warps
#define DOTW     28
#define HMAX     64
#define NCACHE   27           // U-matrix rows cached in SMEM per CTA (big path)
#define ROW_U4   512          // uint4 per weight row (4096 halves = 8 KB)
#define H2_U4    512          // uint4 of packed fp16 h (4096 halves = 8 KB)

// ---------------- persistent device state ----------------------------------
__device__ __half   g_wu[(size_t)H * H];   // fp16 weights, PERMUTED layout:
__device__ __half   g_wr[(size_t)H * H];   // chunk j = cols {4j..4j+3, 2048+4j..2048+4j+3}
__device__ __half   g_wc[(size_t)H * H];
__device__ __half   g_h16[2][H];           // packed-PERMUTED fp16 h (sole cross-CTA state;
                                           // fp32 chain lives in gate-lane registers)
__device__ float    g_vhp[HMAX + 1][GRID];
__device__ unsigned g_count;               // centralized barrier (R8-proven)
__device__ unsigned g_phase;

// ---------------- fp32 -> fp16 conversion with column permutation -----------
__global__ void convert_w(const float* __restrict__ u,
                          const float* __restrict__ r,
                          const float* __restrict__ c)
{
    const int total = H * ROW_U4;
    int idx = blockIdx.x * blockDim.x + threadIdx.x;
    if (idx >= total) return;
    const int row = idx >> 9;
    const int j   = idx & 511;
    const int i0  = row * (H / 4) + j;        // float4 index of cols 4j..4j+3
    const int i1  = i0 + 512;                 // float4 index of cols 2048+4j..+3

    #define CVT_ONE(SRC, DST)                                           \
    {                                                                   \
        float4 a = ((const float4*)SRC)[i0];                            \
        float4 b = ((const float4*)SRC)[i1];                            \
        uint4 o;                                                        \
        __half2 t;                                                      \
        t = __floats2half2_rn(a.x, a.y); o.x = *(unsigned*)&t;          \
        t = __floats2half2_rn(a.z, a.w); o.y = *(unsigned*)&t;          \
        t = __floats2half2_rn(b.x, b.y); o.z = *(unsigned*)&t;          \
        t = __floats2half2_rn(b.z, b.w); o.w = *(unsigned*)&t;          \
        ((uint4*)DST)[idx] = o;                                         \
    }
    CVT_ONE(u, g_wu)
    CVT_ONE(r, g_wr)
    CVT_ONE(c, g_wc)
    #undef CVT_ONE
}

// ---------------- grid-wide barrier (R8-proven centralized version) ----------
__device__ __forceinline__ void grid_barrier(unsigned &local_phase, int G) {
    __threadfence();
    __syncthreads();
    if (threadIdx.x == 0) {
        unsigned target = local_phase + 1;
        unsigned arrived = atomicAdd(&g_count, 1u) + 1;
        if (arrived == (unsigned)G) {
            atomicExch(&g_count, 0u);
            __threadfence();
            atomicAdd(&g_phase, 1u);
        } else {
            volatile unsigned* ph = &g_phase;
            while (*ph < target) { }
        }
    }
    local_phase++;
    __syncthreads();
    __threadfence();
}

__device__ __forceinline__ float sigmoidf_fast(float z) {
    return 1.0f / (1.0f + __expf(-z));
}

// packed f32x2 add: acc(lo,hi) += (x0,x1); acc carried as u64
__device__ __forceinline__ void fadd2(unsigned long long& acc, float x0, float x1)
{
    unsigned long long a;
    asm("mov.b64 %0, {%1, %2};" : "=l"(a) : "f"(x0), "f"(x1));
    asm("add.rn.f32x2 %0, %1, %2;" : "=l"(acc) : "l"(acc), "l"(a));
}

__device__ __forceinline__ float hsum2(unsigned long long acc) {
    float lo, hi;
    asm("mov.b64 {%0, %1}, %2;" : "=f"(lo), "=f"(hi) : "l"(acc));
    return lo + hi;
}

__device__ __forceinline__ __half2 u2h2(unsigned v) { return *(__half2*)&v; }

// 8-element packed-half partial dot: (w uint4) . (h uint4) -> float2
__device__ __forceinline__ float2 dot8h(uint4 w, uint4 h)
{
    __half2 p = __hmul2(u2h2(w.x), u2h2(h.x));
    p = __hfma2(u2h2(w.y), u2h2(h.y), p);
    p = __hfma2(u2h2(w.z), u2h2(h.z), p);
    p = __hfma2(u2h2(w.w), u2h2(h.w), p);
    return __half22float2(p);
}

// spin on 4 per-stager-warp step flags (values are monotone step numbers)
__device__ __forceinline__ void wait_flags(volatile int* f, int t) {
    while (f[0] < t || f[1] < t || f[2] < t || f[3] < t) { }
}

// ---------------- persistent GRU kernel -------------------------------------
__global__ void __launch_bounds__(BLOCK, 1)
gru_persistent(const float* __restrict__ x_seq,
               const float* __restrict__ uwx, const float* __restrict__ ub,
               const float* __restrict__ rwx, const float* __restrict__ rb,
               const float* __restrict__ wx,  const float* __restrict__ bb,
               const float* __restrict__ v,   const float* __restrict__ cc,
               float* __restrict__ out, int horizon, int ncache)
{
    extern __shared__ char smem[];
    uint4* h2s = (uint4*)smem;                          // 8 KB packed fp16 h
    uint4* ws  = (uint4*)(smem + H2_U4 * sizeof(uint4)); // ncache rows of U

    __shared__ float red_s[32];
    __shared__ float gc_s[7][DOTW];      // gate constants per owned row
    __shared__ float x_s;
    __shared__ int   flA[4], flB[4];     // per-stager-warp flags
    __shared__ int   flX;                // x-ready flag (AR phase only)

    const int tid  = threadIdx.x;
    const int b    = blockIdx.x;
    const int G    = gridDim.x;
    const int warp = tid >> 5;
    const int lane = tid & 31;

    const int r0 = (int)(((long long)b       * H) / G);
    const int r1 = (int)(((long long)(b + 1) * H) / G);
    const int nrows = r1 - r0;   // 27 or 28 (<= DOTW)

    if (tid < 4) { flA[tid] = -1; flB[tid] = -1; }
    if (tid == 4) flX = -1;
    if (tid < 32) red_s[tid] = 0.f;
    // stage gate constants into SMEM (row r0+i -> column i)
    if (tid < nrows) {
        const int row = r0 + tid;
        gc_s[0][tid] = uwx[row]; gc_s[1][tid] = ub[row];
        gc_s[2][tid] = rwx[row]; gc_s[3][tid] = rb[row];
        gc_s[4][tid] = wx[row];  gc_s[5][tid] = bb[row];
        gc_s[6][tid] = v[row];
    }

    // prologue: pin first `ncache` U-rows of this CTA into SMEM
    {
        const uint4* src = ((const uint4*)g_wu) + (size_t)r0 * ROW_U4;
        const int n = ncache * ROW_U4;
        for (int i = tid; i < n; i += BLOCK) ws[i] = src[i];
    }

    // matvec row pointers (warp w owns row r0+w for all three matrices)
    const bool mv_active = (warp < nrows);
    const int  myrow = r0 + warp;
    const uint4* pu = nullptr; const uint4* pr = nullptr; const uint4* pc = nullptr;
    if (mv_active) {
        const size_t off = (size_t)myrow * ROW_U4;
        pu = (warp < ncache) ? (ws + (size_t)warp * ROW_U4)
                             : (((const uint4*)g_wu) + off);
        pr = ((const uint4*)g_wr) + off;
        pc = ((const uint4*)g_wc) + off;
    }

    // permuted fp16 write index for this warp's row
    const int h16_idx = (myrow < 2048) ? ((myrow >> 2) * 8 + (myrow & 3))
                                       : (((myrow - 2048) >> 2) * 8 + 4 + (myrow & 3));

    const float c0 = cc[0];
    unsigned phase = 0;
    const int total_steps = T_TRAIN + horizon;
    __syncthreads();   // flags/constants/ws visible to all warps

    // cross-step pipelined lead weights (batch 0 of step 0)
    uint4 wu0 = {0,0,0,0}, wr0 = {0,0,0,0}, wc0 = {0,0,0,0};
    if (warp < DOTW && mv_active) {
        wu0 = pu[lane]; wr0 = pr[lane]; wc0 = pc[lane];
    }

    // fp32 hidden-state chain: lives in lane-0 registers (h0 = 0)
    float hflt = 0.f;

    for (int t = 0; t < total_steps; ++t) {
        const int par = t & 1;
        const bool need_y = (t >= T_TRAIN - 1);

        if (warp >= DOTW) {
            // ---- stager warps: verbatim 8 KB copy of packed fp16 h ----
            const int sw  = warp - DOTW;        // 0..3
            const int sid = tid - DOTW * 32;    // 0..127

            // warp 31: publish x for AR steps only (training x is read directly)
            if (warp == 31 && t >= T_TRAIN) {
                const float* p = g_vhp[t - T_TRAIN];
                float s = 0.f;
                for (int i = lane; i < G; i += 32) s += p[i];
                #pragma unroll
                for (int o = 16; o; o >>= 1)
                    s += __shfl_down_sync(0xffffffffu, s, o);
                if (lane == 0) {
                    x_s = s + c0;
                    __threadfence_block();
                    flX = t;
                }
            }

            const uint4* src16 = (const uint4*)g_h16[par];
            // chunk A: uint4 [0,256)  (dot batches k<8)
            #pragma unroll
            for (int i = sid; i < 256; i += 128) h2s[i] = src16[i];
            __syncwarp();
            __threadfence_block();
            if (lane == 0) flA[sw] = t;
            // chunk B: uint4 [256,512)  (dot batches k>=8)
            #pragma unroll
            for (int i = sid + 256; i < 512; i += 128) h2s[i] = src16[i];
            __syncwarp();
            __threadfence_block();
            if (lane == 0) flB[sw] = t;
        } else if (mv_active) {
            // ---- dot warps: merged 16-batch loop, packed-half partials ----
            // training-phase x: issue the load NOW, consume after the dots
            float x_direct = 0.f;
            if (lane == 0 && t < T_TRAIN) x_direct = __ldg(&x_seq[t]);

            unsigned long long au = 0ull, ar = 0ull, ac = 0ull;

            wait_flags(flA, t);
            #pragma unroll
            for (int k = 0; k < 16; ++k) {
                const int j = lane + 32 * k;   // compile-time offset after unroll
                uint4 nu, nr, nc;
                if (k < 15) {                  // in-step prefetch (folds away)
                    nu = pu[j + 32]; nr = pr[j + 32]; nc = pc[j + 32];
                } else {                       // cross-step prefetch: batch 0 of t+1
                    nu = pu[lane]; nr = pr[lane]; nc = pc[lane];
                }
                if (k == 8) wait_flags(flB, t);
                uint4 hh = h2s[j];             // 8 fp16 h, permuted-packed
                float2 fu = dot8h(wu0, hh);
                float2 fr = dot8h(wr0, hh);
                float2 fc = dot8h(wc0, hh);
                fadd2(au, fu.x, fu.y);
                fadd2(ar, fr.x, fr.y);
                fadd2(ac, fc.x, fc.y);
                wu0 = nu; wr0 = nr; wc0 = nc;  // after k=15: holds t+1 batch 0
            }

            float su = hsum2(au), sr = hsum2(ar), sc = hsum2(ac);
            #pragma unroll
            for (int o = 16; o; o >>= 1) {
                su += __shfl_down_sync(0xffffffffu, su, o);
                sr += __shfl_down_sync(0xffffffffu, sr, o);
                sc += __shfl_down_sync(0xffffffffu, sc, o);
            }

            // decentralized gate: lane 0 updates its own row.
            // fp32 chain carried in register hflt; fp16 mirror published for
            // next step's staging.
            if (lane == 0) {
                float x;
                if (t < T_TRAIN) {
                    x = x_direct;
                } else {
                    volatile int* fx = &flX;
                    while (*fx < t) { }
                    x = x_s;
                }
                const float h_old = hflt;
                const float u  = sigmoidf_fast(gc_s[0][warp] * x + su + gc_s[1][warp]);
                const float r  = sigmoidf_fast(gc_s[2][warp] * x + sr + gc_s[3][warp]);
                const float hh = tanhf(gc_s[4][warp] * x + r * sc + gc_s[5][warp]);
                const float hn = h_old + u * (hh - h_old);
                hflt = hn;
                g_h16[par ^ 1][h16_idx] = __float2half_rn(hn);
                if (need_y) red_s[warp] = gc_s[6][warp] * hn;
            }
        }

        // y partial reduction only on the last horizon+1 steps
        if (need_y) {
            __syncthreads();
            if (warp == 0) {
                float yv = (lane < nrows) ? red_s[lane] : 0.f;
                #pragma unroll
                for (int o = 16; o; o >>= 1)
                    yv += __shfl_down_sync(0xffffffffu, yv, o);
                if (lane == 0) g_vhp[t - (T_TRAIN - 1)][b] = yv;
            }
        }

        grid_barrier(phase, G);   // next-step lead weights in flight during this
    }

    // emit predictions (deterministic final reduction)
    if (b == 0 && tid < horizon) {
        const float* p = g_vhp[tid + 1];
        float s = 0.f;
        for (int i = 0; i < G; ++i) s += p[i];
        out[tid] = s + c0;
    }
}

// ---------------- launch ----------------------------------------------------
extern "C" void kernel_launch(void* const* d_in, const int* in_sizes, int n_in,
                              void* d_out, int out_size)
{
    (void)in_sizes; (void)n_in;
    const float* x_seq = (const float*)d_in[0];
    // d_in[1] is the scalar 'horizon' (int32); we use out_size instead.
    const float* uwx = (const float*)d_in[2];
    const float* uWh = (const float*)d_in[3];
    const float* ub  = (const float*)d_in[4];
    const float* rwx = (const float*)d_in[5];
    const float* rWh = (const float*)d_in[6];
    const float* rb  = (const float*)d_in[7];
    const float* wx  = (const float*)d_in[8];
    const float* Wh  = (const float*)d_in[9];
    const float* bb  = (const float*)d_in[10];
    const float* v   = (const float*)d_in[11];
    const float* cc  = (const float*)d_in[12];

    int horizon = out_size;
    if (horizon > HMAX) horizon = HMAX;

    // reset persistent state (graph-capturable, deterministic per replay)
    void* p;
    cudaGetSymbolAddress(&p, g_h16);   cudaMemsetAsync(p, 0, sizeof(__half) * 2 * H);
    cudaGetSymbolAddress(&p, g_count); cudaMemsetAsync(p, 0, sizeof(unsigned));
    cudaGetSymbolAddress(&p, g_phase); cudaMemsetAsync(p, 0, sizeof(unsigned));

    // fp32 -> fp16 permuted weight conversion
    {
        const int total = H * ROW_U4;
        convert_w<<<(total + 255) / 256, 256>>>(uWh, rWh, Wh);
    }

    // dyn-smem: try 27-row cache, then 26, then none (same decision every call)
    const int base = H2_U4 * (int)sizeof(uint4);      // 8 KB packed fp16 h
    int ncache = NCACHE;
    int dyn    = base + NCACHE * ROW_U4 * (int)sizeof(uint4);
    cudaError_t e = cudaFuncSetAttribute(gru_persistent,
                                         cudaFuncAttributeMaxDynamicSharedMemorySize,
                                         dyn);
    if (e != cudaSuccess) {
        (void)cudaGetLastError();
        ncache = 26;
        dyn    = base + 26 * ROW_U4 * (int)sizeof(uint4);
        e = cudaFuncSetAttribute(gru_persistent,
                                 cudaFuncAttributeMaxDynamicSharedMemorySize,
                                 dyn);
        if (e != cudaSuccess) {
            (void)cudaGetLastError();
            ncache = 0;
            dyn    = base;
        }
    }

    gru_persistent<<<GRID, BLOCK, dyn>>>(x_seq,
                                         uwx, ub,
                                         rwx, rb,
                                         wx,  bb,
                                         v,   cc,
                                         (float*)d_out, horizon, ncache);
}